// round 14
// baseline (speedup 1.0000x reference)
#include <cuda_runtime.h>
#include <math.h>

#define B 64
#define NG 16
#define NSH 112
#define NN 128
#define D 32
#define KQ 8           // features per thread (k-split by 4)
#define KP 4           // packed f32x2 lanes per thread
#define L 5
#define NT 512         // 4 threads per dst node, adjacent lanes

// sV layout (float offsets)
#define VWR   0
#define VB2   32
#define VWATT 64
#define VBQ1  96
#define VWQ2  128
#define VC    160
#define VT0   192
#define VT1   224
#define VBN1  256
#define VBN2  288
#define VBT   320
#define VSC   352   // [VSC]=b_att, [VSC+1]=b_pos2

typedef unsigned long long u64;

__device__ __forceinline__ u64 pk2(float lo, float hi) {
    u64 r; asm("mov.b64 %0, {%1, %2};" : "=l"(r) : "f"(lo), "f"(hi)); return r;
}
__device__ __forceinline__ void upk2(u64 v, float& lo, float& hi) {
    asm("mov.b64 {%0, %1}, %2;" : "=f"(lo), "=f"(hi) : "l"(v));
}
__device__ __forceinline__ u64 f2fma(u64 a, u64 b, u64 c) {
    u64 r; asm("fma.rn.f32x2 %0, %1, %2, %3;" : "=l"(r) : "l"(a), "l"(b), "l"(c)); return r;
}
__device__ __forceinline__ u64 f2add(u64 a, u64 b) {
    u64 r; asm("add.rn.f32x2 %0, %1, %2;" : "=l"(r) : "l"(a), "l"(b)); return r;
}

__device__ __forceinline__ float fsig(float x) {
    return __fdividef(1.f, 1.f + __expf(-x));
}

// One CTA per graph, 512 threads: thread t handles dst node (t>>2) and
// feature quarter (t&3). Each thread loops over ALL 128 srcs for its own 8
// features (4 packed f32x2 lanes); 4-lane exchange via __shfl width=4.
// 4 warps/SMSP for latency hiding. Zero __device__ globals, no clusters,
// ~90 regs (no spill at the 128-reg budget) -> mem guard delta 0.
__global__ void __launch_bounds__(NT, 1)
fused_kernel(const float* __restrict__ pos, const int* __restrict__ ts,
             const float* __restrict__ gpos,
             const float* __restrict__ Whin, const float* __restrict__ bhin,
             const float* __restrict__ Wm1, const float* __restrict__ bm1,
             const float* __restrict__ Wm2, const float* __restrict__ bm2,
             const float* __restrict__ Wat, const float* __restrict__ bat,
             const float* __restrict__ Wq1, const float* __restrict__ bq1,
             const float* __restrict__ Wq2, const float* __restrict__ bq2,
             const float* __restrict__ Wn1, const float* __restrict__ bn1,
             const float* __restrict__ Wn2, const float* __restrict__ bn2,
             const float* __restrict__ Wt, const float* __restrict__ bt,
             float* __restrict__ out) {
    __shared__ float sH[NN * D];     // 16KB node embeddings
    __shared__ float sBig[NN * D];   // 16KB: W staging (rows 0:64), then Bv
    __shared__ float sWa[D * D];     // 4KB: W_msg2 | W_node2
    __shared__ float sWb[D * D];     // 4KB: W_pos1 | W_t
    __shared__ float sP[NN * 2];     // positions
    __shared__ float sV[384];        // small vectors

    int g = blockIdx.x;
    int t = threadIdx.x;
    int dst = t >> 2;
    int kq = t & 3;                  // feature quarter
    int k0 = kq * KQ;
    const unsigned FULL = 0xffffffffu;

    // ---------- init: h, p, temb ----------
    if (kq == 0) {
        const float* wrow = Whin + (dst < NG ? 0 : D);
#pragma unroll
        for (int k = 0; k < D; k++) sH[dst * D + k] = wrow[k] + bhin[k];
        if (dst < NG) { sP[dst * 2] = gpos[dst * 2]; sP[dst * 2 + 1] = gpos[dst * 2 + 1]; }
        else {
            int i = (g * NSH + (dst - NG)) * 2;
            sP[dst * 2] = pos[i]; sP[dst * 2 + 1] = pos[i + 1];
        }
    }
    if (t < D) {
        // no cosf/sinf (slow-path local buffer -> stack frame). Double
        // Cody-Waite reduction (inline) + MUFU sin/cos on [-pi,pi].
        float tf = (float)ts[g];
        int k = (t < 16) ? t : (t - 16);
        float fr = expf(-logf(10000.f) * (float)k / 16.f);
        float angf = tf * fr;
        double ang = (double)angf;
        double q = rint(ang * 0.15915494309189535);
        float r = (float)(ang - q * 6.283185307179586);
        sV[VT0 + t] = (t < 16) ? __cosf(r) : __sinf(r);
    }
    __syncthreads();

    for (int l = 0; l < L; l++) {
        const float* Wm1l = Wm1 + l * 97 * D;
        int trd = (l & 1) ? VT1 : VT0;
        int twr = (l & 1) ? VT0 : VT1;

        // ---- stage message weights ----
        for (int i = t; i < 2 * D * D; i += NT) sBig[i] = Wm1l[i];  // W1 rows 0:64
        for (int i = t; i < D * D; i += NT) {
            sWa[i] = Wm2[l * D * D + i];
            sWb[i] = Wq1[l * D * D + i];
        }
        if (t < D) {
            sV[VWR + t]   = Wm1l[64 * D + t];
            sV[VB2 + t]   = bm2[l * D + t];
            sV[VWATT + t] = Wat[l * D + t];
            sV[VBQ1 + t]  = bq1[l * D + t];
            sV[VWQ2 + t]  = Wq2[l * D + t];
        }
        if (t == 0) { sV[VSC] = bat[l]; sV[VSC + 1] = bq2[l]; }
        __syncthreads();

        // ---- AC (own 8 feats) and Bv (own 8 feats of own node) ----
        float AC[KQ], bv[KQ];
#pragma unroll
        for (int k = 0; k < KQ; k++) { AC[k] = 0.f; bv[k] = 0.f; }
#pragma unroll
        for (int d = 0; d < D; d++) {
            float hv = sH[dst * D + d];
#pragma unroll
            for (int k = 0; k < KQ; k++) {
                AC[k] = fmaf(hv, sBig[d * D + k0 + k], AC[k]);
                bv[k] = fmaf(hv, sBig[(D + d) * D + k0 + k], bv[k]);
            }
        }
        if (t < D) {
            float c = bm1[l * D + t];
#pragma unroll
            for (int d = 0; d < D; d++)
                c = fmaf(sV[trd + d], __ldg(&Wm1l[(65 + d) * D + t]), c);
            sV[VC + t] = c;
        }
        __syncthreads();   // staging reads done
#pragma unroll
        for (int k = 0; k < KQ; k++) sBig[dst * D + k0 + k] = bv[k];
        __syncthreads();   // Bv ready

        // packed loop-invariants
        u64 ACp[KP], wrp[KP];
#pragma unroll
        for (int kk = 0; kk < KP; kk++)
            ACp[kk] = pk2(AC[2 * kk] + sV[VC + k0 + 2 * kk],
                          AC[2 * kk + 1] + sV[VC + k0 + 2 * kk + 1]);
        {
            const ulonglong2* q = (const ulonglong2*)&sV[VWR + k0];
#pragma unroll
            for (int kk = 0; kk < KP / 2; kk++) {
                ulonglong2 w = q[kk];
                wrp[2 * kk] = w.x; wrp[2 * kk + 1] = w.y;
            }
        }

        // ---- edge loop: all 128 srcs, own 8 features (4 f32x2 lanes) ----
        float pix = sP[dst * 2], piy = sP[dst * 2 + 1];
        u64 agghp[KP];
#pragma unroll
        for (int kk = 0; kk < KP; kk++) agghp[kk] = 0ull;
        float apx = 0.f, apy = 0.f;

        for (int j = 0; j < NN; j++) {
            float dx = pix - sP[j * 2];
            float dy = piy - sP[j * 2 + 1];
            float radial = dx * dx + dy * dy;
            float inv = __fdividef(1.f, sqrtf(radial) + 1e-6f);
            float ndx = dx * inv, ndy = dy * inv;
            u64 radp = pk2(radial, radial);

            // m1 = silu(AC + Bv[j] + radial*wr) ; packed preactivation
            float m1[KQ];
            {
                const ulonglong2* bq = (const ulonglong2*)&sBig[j * D + k0];
#pragma unroll
                for (int kk = 0; kk < KP / 2; kk++) {
                    ulonglong2 bw = bq[kk];
                    u64 x0 = f2fma(radp, wrp[2 * kk], f2add(ACp[2 * kk], bw.x));
                    u64 x1 = f2fma(radp, wrp[2 * kk + 1], f2add(ACp[2 * kk + 1], bw.y));
                    float a, b;
                    upk2(x0, a, b);
                    m1[4 * kk]     = a * fsig(a);
                    m1[4 * kk + 1] = b * fsig(b);
                    upk2(x1, a, b);
                    m1[4 * kk + 2] = a * fsig(a);
                    m1[4 * kk + 3] = b * fsig(b);
                }
            }

            // GEMM1: m2 = m1 @ W_msg2 + b2 (packed, width-4 broadcast)
            u64 m2p[KP];
            {
                const ulonglong2* bq = (const ulonglong2*)&sV[VB2 + k0];
#pragma unroll
                for (int kk = 0; kk < KP / 2; kk++) {
                    ulonglong2 bw = bq[kk];
                    m2p[2 * kk] = bw.x; m2p[2 * kk + 1] = bw.y;
                }
            }
#pragma unroll
            for (int d = 0; d < D; d++) {
                float v = __shfl_sync(FULL, m1[d & (KQ - 1)], d >> 3, 4);
                u64 vv = pk2(v, v);
                const ulonglong2* w = (const ulonglong2*)&sWa[d * D + k0];
#pragma unroll
                for (int kk = 0; kk < KP / 2; kk++) {
                    ulonglong2 ww = w[kk];
                    m2p[2 * kk]     = f2fma(vv, ww.x, m2p[2 * kk]);
                    m2p[2 * kk + 1] = f2fma(vv, ww.y, m2p[2 * kk + 1]);
                }
            }
            // silu + attention dot
            float m2[KQ];
            float attp = 0.f;
#pragma unroll
            for (int kk = 0; kk < KP; kk++) {
                float a, b;
                upk2(m2p[kk], a, b);
                a = a * fsig(a); b = b * fsig(b);
                m2[2 * kk] = a; m2[2 * kk + 1] = b;
                attp = fmaf(a, sV[VWATT + k0 + 2 * kk], attp);
                attp = fmaf(b, sV[VWATT + k0 + 2 * kk + 1], attp);
                m2p[kk] = pk2(a, b);          // repack silu'd m2 for aggh
            }
            attp += __shfl_xor_sync(FULL, attp, 1);
            attp += __shfl_xor_sync(FULL, attp, 2);
            float att = fsig(attp + sV[VSC]);
            u64 attp2 = pk2(att, att);

            // GEMM2: acc = m2 @ W_pos1 (packed, width-4 broadcast)
            u64 accp[KP];
#pragma unroll
            for (int kk = 0; kk < KP; kk++) accp[kk] = 0ull;
#pragma unroll
            for (int d = 0; d < D; d++) {
                float v = __shfl_sync(FULL, m2[d & (KQ - 1)], d >> 3, 4);
                u64 vv = pk2(v, v);
                const ulonglong2* w = (const ulonglong2*)&sWb[d * D + k0];
#pragma unroll
                for (int kk = 0; kk < KP / 2; kk++) {
                    ulonglong2 ww = w[kk];
                    accp[2 * kk]     = f2fma(vv, ww.x, accp[2 * kk]);
                    accp[2 * kk + 1] = f2fma(vv, ww.y, accp[2 * kk + 1]);
                }
            }

            // qv/pw chain + aggh accumulate (aggh packed)
            float pwp = 0.f;
            {
                const u64* bq = (const u64*)&sV[VBQ1 + k0];
#pragma unroll
                for (int kk = 0; kk < KP; kk++) {
                    u64 xq = f2fma(attp2, accp[kk], bq[kk]);
                    float a, b;
                    upk2(xq, a, b);
                    a = a * fsig(a); b = b * fsig(b);
                    pwp = fmaf(a, sV[VWQ2 + k0 + 2 * kk], pwp);
                    pwp = fmaf(b, sV[VWQ2 + k0 + 2 * kk + 1], pwp);
                    agghp[kk] = f2fma(attp2, m2p[kk], agghp[kk]);
                }
            }
            pwp += __shfl_xor_sync(FULL, pwp, 1);
            pwp += __shfl_xor_sync(FULL, pwp, 2);
            float pw = pwp + sV[VSC + 1];
            apx = fmaf(ndx, pw, apx);
            apy = fmaf(ndy, pw, apy);
        }
        __syncthreads();   // edge-loop reads of sBig/sP done

        // unpack aggh for the node update
        float aggh[KQ];
#pragma unroll
        for (int kk = 0; kk < KP; kk++)
            upk2(agghp[kk], aggh[2 * kk], aggh[2 * kk + 1]);

        // ---- p update (aggr complete per thread; kq==0 writes) ----
        float px = fmaf(apx, 1.f / NN, pix);
        float py = fmaf(apy, 1.f / NN, piy);
        if (kq == 0) { sP[dst * 2] = px; sP[dst * 2 + 1] = py; }

        if (l == L - 1) {
            if (kq == 0 && dst >= NG) {
                int o = (g * NSH + (dst - NG)) * 2;
                out[o] = px; out[o + 1] = py;
            }
            break;
        }

        // ---- stage node-update weights ----
        for (int i = t; i < 2 * D * D; i += NT) sBig[i] = Wn1[l * 2 * D * D + i];
        for (int i = t; i < D * D; i += NT) {
            sWa[i] = Wn2[l * D * D + i];
            sWb[i] = Wt[l * D * D + i];
        }
        if (t < D) {
            sV[VBN1 + t] = bn1[l * D + t];
            sV[VBN2 + t] = bn2[l * D + t];
            sV[VBT + t]  = bt[l * D + t];
        }
        __syncthreads();

        // ---- node MLP + residual (own 8 feats; aggh/u1 via width-4 shfl) ----
        float u1[KQ];
#pragma unroll
        for (int k = 0; k < KQ; k++) u1[k] = sV[VBN1 + k0 + k];
#pragma unroll
        for (int d = 0; d < D; d++) {
            float hv = sH[dst * D + d];
#pragma unroll
            for (int k = 0; k < KQ; k++)
                u1[k] = fmaf(hv, sBig[d * D + k0 + k], u1[k]);
        }
#pragma unroll
        for (int d = 0; d < D; d++) {
            float av = __shfl_sync(FULL, aggh[d & (KQ - 1)], d >> 3, 4);
#pragma unroll
            for (int k = 0; k < KQ; k++)
                u1[k] = fmaf(av, sBig[(D + d) * D + k0 + k], u1[k]);
        }
#pragma unroll
        for (int k = 0; k < KQ; k++) u1[k] = u1[k] * fsig(u1[k]);
        float u2[KQ];
#pragma unroll
        for (int k = 0; k < KQ; k++) u2[k] = sV[VBN2 + k0 + k];
#pragma unroll
        for (int d = 0; d < D; d++) {
            float uv = __shfl_sync(FULL, u1[d & (KQ - 1)], d >> 3, 4);
#pragma unroll
            for (int k = 0; k < KQ; k++)
                u2[k] = fmaf(uv, sWa[d * D + k0 + k], u2[k]);
        }
        float hnew[KQ];
#pragma unroll
        for (int k = 0; k < KQ; k++) {
            float u = u2[k];
            hnew[k] = (u > 0.f ? u : 0.01f * u) + sH[dst * D + k0 + k];
        }
        __syncthreads();   // all sH reads done before partial-row writes
#pragma unroll
        for (int k = 0; k < KQ; k++) sH[dst * D + k0 + k] = hnew[k];
        if (t < D) {
            float acc = sV[VBT + t];
#pragma unroll
            for (int d = 0; d < D; d++) acc = fmaf(sV[trd + d], sWb[d * D + t], acc);
            sV[twr + t] = acc * fsig(acc);
        }
        __syncthreads();   // h/temb updated before next layer
    }
}

extern "C" void kernel_launch(void* const* d_in, const int* in_sizes, int n_in,
                              void* d_out, int out_size) {
    const float* pos  = (const float*)d_in[0];
    const int*   ts   = (const int*)d_in[1];
    const float* gpos = (const float*)d_in[2];
    const float* Whin = (const float*)d_in[3];
    const float* bhin = (const float*)d_in[4];
    const float* Wm1  = (const float*)d_in[5];
    const float* bm1  = (const float*)d_in[6];
    const float* Wm2  = (const float*)d_in[7];
    const float* bm2  = (const float*)d_in[8];
    const float* Wat  = (const float*)d_in[9];
    const float* bat  = (const float*)d_in[10];
    const float* Wq1  = (const float*)d_in[11];
    const float* bq1  = (const float*)d_in[12];
    const float* Wq2  = (const float*)d_in[13];
    const float* bq2  = (const float*)d_in[14];
    const float* Wn1  = (const float*)d_in[15];
    const float* bn1  = (const float*)d_in[16];
    const float* Wn2  = (const float*)d_in[17];
    const float* bn2  = (const float*)d_in[18];
    const float* Wt   = (const float*)d_in[19];
    const float* bt   = (const float*)d_in[20];
    float* out = (float*)d_out;

    fused_kernel<<<B, NT>>>(pos, ts, gpos, Whin, bhin,
                            Wm1, bm1, Wm2, bm2, Wat, bat,
                            Wq1, bq1, Wq2, bq2,
                            Wn1, bn1, Wn2, bn2, Wt, bt, out);
}

// round 16
// speedup vs baseline: 2.0057x; 2.0057x over previous
#include <cuda_runtime.h>
#include <math.h>

#define B 64
#define NG 16
#define NSH 112
#define NN 128
#define D 32
#define KH 16          // features per thread (k-split by 2)
#define KV 8           // packed f32x2 lanes per thread
#define L 5
#define NT 256         // 2 threads per dst node, adjacent lanes

// sV layout (float offsets)
#define VWR   0
#define VB2   32
#define VWATT 64
#define VBQ1  96
#define VWQ2  128
#define VC    160
#define VT0   192
#define VT1   224
#define VBN1  256
#define VBN2  288
#define VBT   320
#define VSC   352   // [VSC]=b_att, [VSC+1]=b_pos2

typedef unsigned long long u64;

__device__ __forceinline__ u64 pk2(float lo, float hi) {
    u64 r; asm("mov.b64 %0, {%1, %2};" : "=l"(r) : "f"(lo), "f"(hi)); return r;
}
__device__ __forceinline__ void upk2(u64 v, float& lo, float& hi) {
    asm("mov.b64 {%0, %1}, %2;" : "=f"(lo), "=f"(hi) : "l"(v));
}
__device__ __forceinline__ u64 f2fma(u64 a, u64 b, u64 c) {
    u64 r; asm("fma.rn.f32x2 %0, %1, %2, %3;" : "=l"(r) : "l"(a), "l"(b), "l"(c)); return r;
}
__device__ __forceinline__ u64 f2add(u64 a, u64 b) {
    u64 r; asm("add.rn.f32x2 %0, %1, %2;" : "=l"(r) : "l"(a), "l"(b)); return r;
}

// sigmoid via single-MUFU tanh.approx: sig(x) = 0.5*tanh(0.5x) + 0.5
__device__ __forceinline__ float fsig(float x) {
    float t;
    asm("tanh.approx.f32 %0, %1;" : "=f"(t) : "f"(x * 0.5f));
    return fmaf(t, 0.5f, 0.5f);
}

// One CTA per graph, 256 threads: thread t handles dst node (t>>1) and
// feature half (t&1). Each thread loops over ALL 128 srcs for its own 16
// features (8 packed f32x2 lanes). Pair exchange: 16 batched xor-shfls per
// GEMM, then both halves' activations are register operands (each lane
// walks its own 16 weight rows then the partner's 16). Zero __device__
// globals, no clusters, no spill -> mem guard delta 0.
__global__ void __launch_bounds__(NT, 1)
fused_kernel(const float* __restrict__ pos, const int* __restrict__ ts,
             const float* __restrict__ gpos,
             const float* __restrict__ Whin, const float* __restrict__ bhin,
             const float* __restrict__ Wm1, const float* __restrict__ bm1,
             const float* __restrict__ Wm2, const float* __restrict__ bm2,
             const float* __restrict__ Wat, const float* __restrict__ bat,
             const float* __restrict__ Wq1, const float* __restrict__ bq1,
             const float* __restrict__ Wq2, const float* __restrict__ bq2,
             const float* __restrict__ Wn1, const float* __restrict__ bn1,
             const float* __restrict__ Wn2, const float* __restrict__ bn2,
             const float* __restrict__ Wt, const float* __restrict__ bt,
             float* __restrict__ out) {
    __shared__ float sH[NN * D];     // 16KB node embeddings
    __shared__ float sBig[NN * D];   // 16KB: W staging (rows 0:64), then Bv
    __shared__ float sWa[D * D];     // 4KB: W_msg2 | W_node2
    __shared__ float sWb[D * D];     // 4KB: W_pos1 | W_t
    __shared__ float sP[NN * 2];     // positions
    __shared__ float sV[384];        // small vectors

    int g = blockIdx.x;
    int t = threadIdx.x;
    int dst = t >> 1;
    int kh = t & 1;                  // feature half
    int k0 = kh * KH;
    int k1 = k0 ^ KH;                // partner's half offset
    const unsigned FULL = 0xffffffffu;

    // ---------- init: h, p, temb ----------
    if (kh == 0) {
        const float* wrow = Whin + (dst < NG ? 0 : D);
#pragma unroll
        for (int k = 0; k < D; k++) sH[dst * D + k] = wrow[k] + bhin[k];
        if (dst < NG) { sP[dst * 2] = gpos[dst * 2]; sP[dst * 2 + 1] = gpos[dst * 2 + 1]; }
        else {
            int i = (g * NSH + (dst - NG)) * 2;
            sP[dst * 2] = pos[i]; sP[dst * 2 + 1] = pos[i + 1];
        }
    }
    if (t < D) {
        // no cosf/sinf (slow-path local buffer -> stack frame). Double
        // Cody-Waite reduction (inline) + MUFU sin/cos on [-pi,pi].
        float tf = (float)ts[g];
        int k = (t < 16) ? t : (t - 16);
        float fr = expf(-logf(10000.f) * (float)k / 16.f);
        float angf = tf * fr;
        double ang = (double)angf;
        double q = rint(ang * 0.15915494309189535);
        float r = (float)(ang - q * 6.283185307179586);
        sV[VT0 + t] = (t < 16) ? __cosf(r) : __sinf(r);
    }
    __syncthreads();

    for (int l = 0; l < L; l++) {
        const float* Wm1l = Wm1 + l * 97 * D;
        int trd = (l & 1) ? VT1 : VT0;
        int twr = (l & 1) ? VT0 : VT1;

        // ---- stage message weights ----
        for (int i = t; i < 2 * D * D; i += NT) sBig[i] = Wm1l[i];  // W1 rows 0:64
        for (int i = t; i < D * D; i += NT) {
            sWa[i] = Wm2[l * D * D + i];
            sWb[i] = Wq1[l * D * D + i];
        }
        if (t < D) {
            sV[VWR + t]   = Wm1l[64 * D + t];
            sV[VB2 + t]   = bm2[l * D + t];
            sV[VWATT + t] = Wat[l * D + t];
            sV[VBQ1 + t]  = bq1[l * D + t];
            sV[VWQ2 + t]  = Wq2[l * D + t];
        }
        if (t == 0) { sV[VSC] = bat[l]; sV[VSC + 1] = bq2[l]; }
        __syncthreads();

        // ---- AC (own 16 feats) and Bv (own 16 feats of own node) ----
        float AC[KH], bv[KH];
#pragma unroll
        for (int k = 0; k < KH; k++) { AC[k] = 0.f; bv[k] = 0.f; }
#pragma unroll
        for (int d = 0; d < D; d++) {
            float hv = sH[dst * D + d];
#pragma unroll
            for (int k = 0; k < KH; k++) {
                AC[k] = fmaf(hv, sBig[d * D + k0 + k], AC[k]);
                bv[k] = fmaf(hv, sBig[(D + d) * D + k0 + k], bv[k]);
            }
        }
        if (t < D) {
            float c = bm1[l * D + t];
#pragma unroll
            for (int d = 0; d < D; d++)
                c = fmaf(sV[trd + d], __ldg(&Wm1l[(65 + d) * D + t]), c);
            sV[VC + t] = c;
        }
        __syncthreads();   // staging reads done
#pragma unroll
        for (int k = 0; k < KH; k++) sBig[dst * D + k0 + k] = bv[k];
        __syncthreads();   // Bv ready

        // packed loop-invariants
        u64 ACp[KV], wrp[KV];
#pragma unroll
        for (int kk = 0; kk < KV; kk++)
            ACp[kk] = pk2(AC[2 * kk] + sV[VC + k0 + 2 * kk],
                          AC[2 * kk + 1] + sV[VC + k0 + 2 * kk + 1]);
        {
            const ulonglong2* q = (const ulonglong2*)&sV[VWR + k0];
#pragma unroll
            for (int kk = 0; kk < KV / 2; kk++) {
                ulonglong2 w = q[kk];
                wrp[2 * kk] = w.x; wrp[2 * kk + 1] = w.y;
            }
        }

        // ---- edge loop: all 128 srcs, own 16 features (8 f32x2 lanes) ----
        float pix = sP[dst * 2], piy = sP[dst * 2 + 1];
        u64 agghp[KV];
#pragma unroll
        for (int kk = 0; kk < KV; kk++) agghp[kk] = 0ull;
        float apx = 0.f, apy = 0.f;

        for (int j = 0; j < NN; j++) {
            float dx = pix - sP[j * 2];
            float dy = piy - sP[j * 2 + 1];
            float radial = dx * dx + dy * dy;
            float inv = __fdividef(1.f, sqrtf(radial) + 1e-6f);
            float ndx = dx * inv, ndy = dy * inv;
            u64 radp = pk2(radial, radial);

            // m1 = silu(AC + Bv[j] + radial*wr) ; packed preactivation
            float m1[KH];
            {
                const ulonglong2* bq = (const ulonglong2*)&sBig[j * D + k0];
#pragma unroll
                for (int kk = 0; kk < KV / 2; kk++) {
                    ulonglong2 bw = bq[kk];
                    u64 x0 = f2fma(radp, wrp[2 * kk], f2add(ACp[2 * kk], bw.x));
                    u64 x1 = f2fma(radp, wrp[2 * kk + 1], f2add(ACp[2 * kk + 1], bw.y));
                    float a, b;
                    upk2(x0, a, b);
                    m1[4 * kk]     = a * fsig(a);
                    m1[4 * kk + 1] = b * fsig(b);
                    upk2(x1, a, b);
                    m1[4 * kk + 2] = a * fsig(a);
                    m1[4 * kk + 3] = b * fsig(b);
                }
            }
            // batched pair exchange of m1 (partner's half)
            float mo1[KH];
#pragma unroll
            for (int i = 0; i < KH; i++) mo1[i] = __shfl_xor_sync(FULL, m1[i], 1);

            // GEMM1: m2 = m1 @ W_msg2 + b2 (register activations, two
            // row-walks: own half rows k0+i, partner half rows k1+i)
            u64 m2p[KV];
            {
                const ulonglong2* bq = (const ulonglong2*)&sV[VB2 + k0];
#pragma unroll
                for (int kk = 0; kk < KV / 2; kk++) {
                    ulonglong2 bw = bq[kk];
                    m2p[2 * kk] = bw.x; m2p[2 * kk + 1] = bw.y;
                }
            }
#pragma unroll
            for (int i = 0; i < KH; i++) {
                u64 vv = pk2(m1[i], m1[i]);
                const ulonglong2* w = (const ulonglong2*)&sWa[(k0 + i) * D + k0];
#pragma unroll
                for (int kk = 0; kk < KV / 2; kk++) {
                    ulonglong2 ww = w[kk];
                    m2p[2 * kk]     = f2fma(vv, ww.x, m2p[2 * kk]);
                    m2p[2 * kk + 1] = f2fma(vv, ww.y, m2p[2 * kk + 1]);
                }
                u64 vo = pk2(mo1[i], mo1[i]);
                const ulonglong2* w2 = (const ulonglong2*)&sWa[(k1 + i) * D + k0];
#pragma unroll
                for (int kk = 0; kk < KV / 2; kk++) {
                    ulonglong2 ww = w2[kk];
                    m2p[2 * kk]     = f2fma(vo, ww.x, m2p[2 * kk]);
                    m2p[2 * kk + 1] = f2fma(vo, ww.y, m2p[2 * kk + 1]);
                }
            }
            // silu + attention dot
            float m2[KH];
            float attp = 0.f;
#pragma unroll
            for (int kk = 0; kk < KV; kk++) {
                float a, b;
                upk2(m2p[kk], a, b);
                a = a * fsig(a); b = b * fsig(b);
                m2[2 * kk] = a; m2[2 * kk + 1] = b;
                attp = fmaf(a, sV[VWATT + k0 + 2 * kk], attp);
                attp = fmaf(b, sV[VWATT + k0 + 2 * kk + 1], attp);
                m2p[kk] = pk2(a, b);          // repack silu'd m2 for aggh
            }
            attp += __shfl_xor_sync(FULL, attp, 1);
            float att = fsig(attp + sV[VSC]);
            u64 attp2 = pk2(att, att);

            // batched pair exchange of m2
            float mo2[KH];
#pragma unroll
            for (int i = 0; i < KH; i++) mo2[i] = __shfl_xor_sync(FULL, m2[i], 1);

            // GEMM2: acc = m2 @ W_pos1 (register activations)
            u64 accp[KV];
#pragma unroll
            for (int kk = 0; kk < KV; kk++) accp[kk] = 0ull;
#pragma unroll
            for (int i = 0; i < KH; i++) {
                u64 vv = pk2(m2[i], m2[i]);
                const ulonglong2* w = (const ulonglong2*)&sWb[(k0 + i) * D + k0];
#pragma unroll
                for (int kk = 0; kk < KV / 2; kk++) {
                    ulonglong2 ww = w[kk];
                    accp[2 * kk]     = f2fma(vv, ww.x, accp[2 * kk]);
                    accp[2 * kk + 1] = f2fma(vv, ww.y, accp[2 * kk + 1]);
                }
                u64 vo = pk2(mo2[i], mo2[i]);
                const ulonglong2* w2 = (const ulonglong2*)&sWb[(k1 + i) * D + k0];
#pragma unroll
                for (int kk = 0; kk < KV / 2; kk++) {
                    ulonglong2 ww = w2[kk];
                    accp[2 * kk]     = f2fma(vo, ww.x, accp[2 * kk]);
                    accp[2 * kk + 1] = f2fma(vo, ww.y, accp[2 * kk + 1]);
                }
            }

            // qv/pw chain + aggh accumulate (aggh packed)
            float pwp = 0.f;
            {
                const u64* bq = (const u64*)&sV[VBQ1 + k0];
#pragma unroll
                for (int kk = 0; kk < KV; kk++) {
                    u64 xq = f2fma(attp2, accp[kk], bq[kk]);
                    float a, b;
                    upk2(xq, a, b);
                    a = a * fsig(a); b = b * fsig(b);
                    pwp = fmaf(a, sV[VWQ2 + k0 + 2 * kk], pwp);
                    pwp = fmaf(b, sV[VWQ2 + k0 + 2 * kk + 1], pwp);
                    agghp[kk] = f2fma(attp2, m2p[kk], agghp[kk]);
                }
            }
            pwp += __shfl_xor_sync(FULL, pwp, 1);
            float pw = pwp + sV[VSC + 1];
            apx = fmaf(ndx, pw, apx);
            apy = fmaf(ndy, pw, apy);
        }
        __syncthreads();   // edge-loop reads of sBig/sP done

        // unpack aggh for the node update
        float aggh[KH];
#pragma unroll
        for (int kk = 0; kk < KV; kk++)
            upk2(agghp[kk], aggh[2 * kk], aggh[2 * kk + 1]);

        // ---- p update (aggr complete per thread; kh==0 writes) ----
        float px = fmaf(apx, 1.f / NN, pix);
        float py = fmaf(apy, 1.f / NN, piy);
        if (kh == 0) { sP[dst * 2] = px; sP[dst * 2 + 1] = py; }

        if (l == L - 1) {
            if (kh == 0 && dst >= NG) {
                int o = (g * NSH + (dst - NG)) * 2;
                out[o] = px; out[o + 1] = py;
            }
            break;
        }

        // ---- stage node-update weights ----
        for (int i = t; i < 2 * D * D; i += NT) sBig[i] = Wn1[l * 2 * D * D + i];
        for (int i = t; i < D * D; i += NT) {
            sWa[i] = Wn2[l * D * D + i];
            sWb[i] = Wt[l * D * D + i];
        }
        if (t < D) {
            sV[VBN1 + t] = bn1[l * D + t];
            sV[VBN2 + t] = bn2[l * D + t];
            sV[VBT + t]  = bt[l * D + t];
        }
        __syncthreads();

        // ---- node MLP + residual (own 16 feats; aggh/u1 via pair shfl) ----
        float u1[KH];
#pragma unroll
        for (int k = 0; k < KH; k++) u1[k] = sV[VBN1 + k0 + k];
#pragma unroll
        for (int d = 0; d < D; d++) {
            float hv = sH[dst * D + d];
#pragma unroll
            for (int k = 0; k < KH; k++)
                u1[k] = fmaf(hv, sBig[d * D + k0 + k], u1[k]);
        }
#pragma unroll
        for (int d = 0; d < D; d++) {
            float av = __shfl_sync(FULL, aggh[d & (KH - 1)], d >> 4, 2);
#pragma unroll
            for (int k = 0; k < KH; k++)
                u1[k] = fmaf(av, sBig[(D + d) * D + k0 + k], u1[k]);
        }
#pragma unroll
        for (int k = 0; k < KH; k++) u1[k] = u1[k] * fsig(u1[k]);
        float u2[KH];
#pragma unroll
        for (int k = 0; k < KH; k++) u2[k] = sV[VBN2 + k0 + k];
#pragma unroll
        for (int d = 0; d < D; d++) {
            float uv = __shfl_sync(FULL, u1[d & (KH - 1)], d >> 4, 2);
#pragma unroll
            for (int k = 0; k < KH; k++)
                u2[k] = fmaf(uv, sWa[d * D + k0 + k], u2[k]);
        }
        float hnew[KH];
#pragma unroll
        for (int k = 0; k < KH; k++) {
            float u = u2[k];
            hnew[k] = (u > 0.f ? u : 0.01f * u) + sH[dst * D + k0 + k];
        }
        __syncthreads();   // all sH reads done before partial-row writes
#pragma unroll
        for (int k = 0; k < KH; k++) sH[dst * D + k0 + k] = hnew[k];
        if (t < D) {
            float acc = sV[VBT + t];
#pragma unroll
            for (int d = 0; d < D; d++) acc = fmaf(sV[trd + d], sWb[d * D + t], acc);
            sV[twr + t] = acc * fsig(acc);
        }
        __syncthreads();   // h/temb updated before next layer
    }
}

extern "C" void kernel_launch(void* const* d_in, const int* in_sizes, int n_in,
                              void* d_out, int out_size) {
    const float* pos  = (const float*)d_in[0];
    const int*   ts   = (const int*)d_in[1];
    const float* gpos = (const float*)d_in[2];
    const float* Whin = (const float*)d_in[3];
    const float* bhin = (const float*)d_in[4];
    const float* Wm1  = (const float*)d_in[5];
    const float* bm1  = (const float*)d_in[6];
    const float* Wm2  = (const float*)d_in[7];
    const float* bm2  = (const float*)d_in[8];
    const float* Wat  = (const float*)d_in[9];
    const float* bat  = (const float*)d_in[10];
    const float* Wq1  = (const float*)d_in[11];
    const float* bq1  = (const float*)d_in[12];
    const float* Wq2  = (const float*)d_in[13];
    const float* bq2  = (const float*)d_in[14];
    const float* Wn1  = (const float*)d_in[15];
    const float* bn1  = (const float*)d_in[16];
    const float* Wn2  = (const float*)d_in[17];
    const float* bn2  = (const float*)d_in[18];
    const float* Wt   = (const float*)d_in[19];
    const float* bt   = (const float*)d_in[20];
    float* out = (float*)d_out;

    fused_kernel<<<B, NT>>>(pos, ts, gpos, Whin, bhin,
                            Wm1, bm1, Wm2, bm2, Wat, bat,
                            Wq1, bq1, Wq2, bq2,
                            Wn1, bn1, Wn2, bn2, Wt, bt, out);
}